// round 1
// baseline (speedup 1.0000x reference)
#include <cuda_runtime.h>

// SobelEdge3D: out = sqrt(ed^2 + eh^2 + ew^2 + 1e-6)
// Separable decomposition:
//   per plane p:  gw(h,w) = x(h,w+1)-x(h,w-1),  sw(h,w) = x(h,w-1)+2x(h,w)+x(h,w+1)
//   A(p) = gw(h-1)+2gw(h)+gw(h+1)   -> ed(t) = A(t-1)+2A(t)+A(t+1)
//   B(p) = sw(h+1)-sw(h-1)          -> eh(t) = B(t-1)+2B(t)+B(t+1)
//   C(p) = sw(h-1)+2sw(h)+sw(h+1)   -> ew(t) = C(t+1)-C(t-1)
// Zero padding on every axis (conv padding=1).

constexpr int Wd  = 128;
constexpr int Hd  = 128;
constexpr int Dd  = 64;
constexpr int BCn = 32;     // B*C = 2*16
constexpr int HT  = 8;      // h rows per block
constexpr int ND  = 16;     // d outputs per block
constexpr int ROWS = HT + 2;

__device__ __forceinline__ float rsqrt_approx(float v) {
    float r;
    asm("rsqrt.approx.f32 %0, %1;" : "=f"(r) : "f"(v));
    return r;
}

__global__ __launch_bounds__(256, 2)
void sobel3d_kernel(const float* __restrict__ x, float* __restrict__ out)
{
    __shared__ float sm[ROWS][Wd];   // sm[r][w] = x[p][h0-1+r][w]

    const int tx  = threadIdx.x;          // 0..31  -> w = 4*tx .. 4*tx+3
    const int ty  = threadIdx.y;          // 0..7   -> h = h0 + ty
    const int tid = (ty << 5) | tx;
    const int h0  = blockIdx.x * HT;
    const int d0  = blockIdx.y * ND;
    const long long cbase = (long long)blockIdx.z * Dd * Hd * Wd;

    const int h = h0 + ty;
    const float* __restrict__ xb = x + cbase;
    float* __restrict__ ob = out + cbase + (long long)h * Wd + (tx << 2);

    // Computes per-plane (A,B,C) for this thread's 4 w positions.
    auto plane = [&](int p, float (&A)[4], float (&B)[4], float (&C)[4]) {
        if ((unsigned)p >= (unsigned)Dd) {
            #pragma unroll
            for (int j = 0; j < 4; ++j) { A[j] = 0.f; B[j] = 0.f; C[j] = 0.f; }
            return;
        }
        __syncthreads();   // protect previous plane's reads before overwrite
        const float* __restrict__ xp = xb + (long long)p * Hd * Wd;
        #pragma unroll
        for (int i = tid; i < ROWS * 32; i += 256) {   // 320 float4 per plane
            int r  = i >> 5;
            int c  = i & 31;
            int hh = h0 - 1 + r;
            float4 v = make_float4(0.f, 0.f, 0.f, 0.f);
            if ((unsigned)hh < (unsigned)Hd)
                v = *(const float4*)(xp + hh * Wd + (c << 2));
            *(float4*)&sm[r][c << 2] = v;
        }
        __syncthreads();

        float gw[3][4], sw[3][4];
        #pragma unroll
        for (int r = 0; r < 3; ++r) {
            float4 q = *(const float4*)&sm[ty + r][tx << 2];
            float lf = __shfl_up_sync(0xffffffffu, q.w, 1);
            float rt = __shfl_down_sync(0xffffffffu, q.x, 1);
            if (tx == 0)  lf = 0.f;   // x[-1]  = 0 (zero pad)
            if (tx == 31) rt = 0.f;   // x[128] = 0 (zero pad)
            gw[r][0] = q.y - lf;
            gw[r][1] = q.z - q.x;
            gw[r][2] = q.w - q.y;
            gw[r][3] = rt  - q.z;
            sw[r][0] = lf  + 2.f * q.x + q.y;
            sw[r][1] = q.x + 2.f * q.y + q.z;
            sw[r][2] = q.y + 2.f * q.z + q.w;
            sw[r][3] = q.z + 2.f * q.w + rt;
        }
        #pragma unroll
        for (int j = 0; j < 4; ++j) {
            A[j] = gw[0][j] + 2.f * gw[1][j] + gw[2][j];
            B[j] = sw[2][j] - sw[0][j];
            C[j] = sw[0][j] + 2.f * sw[1][j] + sw[2][j];
        }
    };

    // Streaming d-accumulators:
    //  (ed0,eh0,ew0): output t (emitted after plane t+1 arrives)
    //  (ed1,eh1,ew1): output t+1 partial
    float ed0[4], eh0[4], ew0[4], ed1[4], eh1[4], ew1[4];
    float a[4], b[4], c[4];

    plane(d0 - 1, a, b, c);
    #pragma unroll
    for (int j = 0; j < 4; ++j) {
        ed0[j] = a[j]; eh0[j] = b[j]; ew0[j] = -c[j];
    }
    plane(d0, a, b, c);
    #pragma unroll
    for (int j = 0; j < 4; ++j) {
        ed0[j] += 2.f * a[j];
        eh0[j] += 2.f * b[j];
        ed1[j] = a[j]; eh1[j] = b[j]; ew1[j] = -c[j];
    }

    for (int t = d0; t < d0 + ND; ++t) {
        plane(t + 1, a, b, c);
        float res[4];
        #pragma unroll
        for (int j = 0; j < 4; ++j) {
            float ed = ed0[j] + a[j];
            float eh = eh0[j] + b[j];
            float ew = ew0[j] + c[j];
            float m  = ed * ed + eh * eh + ew * ew + 1e-6f;
            res[j] = m * rsqrt_approx(m);    // sqrt(m), ~2^-22 rel err
            ed0[j] = ed1[j] + 2.f * a[j];
            eh0[j] = eh1[j] + 2.f * b[j];
            ew0[j] = ew1[j];
            ed1[j] = a[j]; eh1[j] = b[j]; ew1[j] = -c[j];
        }
        float4 o = make_float4(res[0], res[1], res[2], res[3]);
        *(float4*)(ob + (long long)t * Hd * Wd) = o;
    }
}

extern "C" void kernel_launch(void* const* d_in, const int* in_sizes, int n_in,
                              void* d_out, int out_size)
{
    const float* x = (const float*)d_in[0];
    float* out = (float*)d_out;
    dim3 grid(Hd / HT, Dd / ND, BCn);   // (16, 4, 32) = 2048 blocks
    dim3 block(32, 8);                  // 256 threads, 4 w per thread (float4)
    sobel3d_kernel<<<grid, block>>>(x, out);
}

// round 2
// speedup vs baseline: 1.6742x; 1.6742x over previous
#include <cuda_runtime.h>

// SobelEdge3D: out = sqrt(ed^2 + eh^2 + ew^2 + 1e-6)
// Separable Sobel; per plane p compute per-thread (A,B,C) for 4 w-positions:
//   gw(h,w) = x(h,w+1)-x(h,w-1),  sw(h,w) = x(h,w-1)+2x(h,w)+x(h,w+1)
//   A = gw(h-1)+2gw(h)+gw(h+1);  B = sw(h+1)-sw(h-1);  C = sw(h-1)+2sw(h)+sw(h+1)
//   ed(t)=A(t-1)+2A(t)+A(t+1); eh likewise from B; ew(t)=C(t+1)-C(t-1)
// No shared memory, no barriers: direct global loads (L1 absorbs h-overlap),
// register double-buffer software pipeline over d.

constexpr int Wd  = 128;
constexpr int Hd  = 128;
constexpr int Dd  = 64;
constexpr int BCn = 32;          // B*C = 2*16
constexpr int HT  = 8;           // h rows per block (one warp per h row)
constexpr int ND  = 16;          // d outputs per block
constexpr int HW  = Hd * Wd;

__device__ __forceinline__ float rsqrt_approx(float v) {
    float r;
    asm("rsqrt.approx.f32 %0, %1;" : "=f"(r) : "f"(v));
    return r;
}

__global__ __launch_bounds__(256, 2)
void sobel3d_kernel(const float* __restrict__ x, float* __restrict__ out)
{
    const int tx = threadIdx.x;                 // 0..31 -> w = 4*tx..4*tx+3
    const int ty = threadIdx.y;                 // 0..7  -> h row (warp-uniform)
    const int h0 = blockIdx.x * HT;
    const int d0 = blockIdx.y * ND;
    const int h  = h0 + ty;
    const long long cb = (long long)blockIdx.z * Dd * HW;

    const float* __restrict__ xr = x + cb + (long long)h * Wd + (tx << 2);
    float* __restrict__ orow = out + cb + (long long)d0 * HW
                                   + (long long)h * Wd + (tx << 2);
    const bool hm = (h > 0);
    const bool hp = (h < Hd - 1);

    // Load one plane's 3 rows (h-1,h,h+1) for this thread's 4 w positions.
    auto ld = [&](int p, float4& q0, float4& q1, float4& q2) {
        const float4 z = make_float4(0.f, 0.f, 0.f, 0.f);
        if ((unsigned)p >= (unsigned)Dd) { q0 = z; q1 = z; q2 = z; return; }
        const float* b = xr + (long long)p * HW;
        q0 = hm ? __ldg((const float4*)(b - Wd)) : z;
        q1 =      __ldg((const float4*)(b));
        q2 = hp ? __ldg((const float4*)(b + Wd)) : z;
    };

    // Per-plane reduction to A,B,C (4 w positions each).
    auto abc = [&](const float4& q0, const float4& q1, const float4& q2,
                   float (&A)[4], float (&B)[4], float (&C)[4]) {
        float gw[3][4], sw[3][4];
        const float4 qs[3] = {q0, q1, q2};
        #pragma unroll
        for (int r = 0; r < 3; ++r) {
            float4 q = qs[r];
            float lf = __shfl_up_sync(0xffffffffu, q.w, 1);
            float rt = __shfl_down_sync(0xffffffffu, q.x, 1);
            if (tx == 0)  lf = 0.f;     // zero pad w = -1
            if (tx == 31) rt = 0.f;     // zero pad w = 128
            gw[r][0] = q.y - lf;
            gw[r][1] = q.z - q.x;
            gw[r][2] = q.w - q.y;
            gw[r][3] = rt  - q.z;
            sw[r][0] = lf  + 2.f * q.x + q.y;
            sw[r][1] = q.x + 2.f * q.y + q.z;
            sw[r][2] = q.y + 2.f * q.z + q.w;
            sw[r][3] = q.z + 2.f * q.w + rt;
        }
        #pragma unroll
        for (int j = 0; j < 4; ++j) {
            A[j] = gw[0][j] + 2.f * gw[1][j] + gw[2][j];
            B[j] = sw[2][j] - sw[0][j];
            C[j] = sw[0][j] + 2.f * sw[1][j] + sw[2][j];
        }
    };

    float a[4], bb[4], cc[4];
    float ed0[4], eh0[4], ew0[4], ed1[4], eh1[4], ew1[4];
    float4 P0, P1, P2, Q0, Q1, Q2;   // double-buffered plane rows

    // Prologue: planes d0-1 and d0.
    ld(d0 - 1, P0, P1, P2);
    ld(d0,     Q0, Q1, Q2);

    abc(P0, P1, P2, a, bb, cc);
    #pragma unroll
    for (int j = 0; j < 4; ++j) {
        ed0[j] = a[j]; eh0[j] = bb[j]; ew0[j] = -cc[j];
    }

    ld(d0 + 1, P0, P1, P2);           // prefetch plane d0+1 into P
    abc(Q0, Q1, Q2, a, bb, cc);
    #pragma unroll
    for (int j = 0; j < 4; ++j) {
        ed0[j] += 2.f * a[j];
        eh0[j] += 2.f * bb[j];
        ed1[j] = a[j]; eh1[j] = bb[j]; ew1[j] = -cc[j];
    }

    // Steady state: at iteration i, buffer (i even ? P : Q) holds plane t+1;
    // prefetch plane t+2 into the other buffer.
    #pragma unroll
    for (int i = 0; i < ND; ++i) {
        const int t = d0 + i;
        const int pn = (i < ND - 1) ? (t + 2) : Dd;   // Dd => zero-fill, no loads
        if (i & 1) {
            ld(pn, P0, P1, P2);
            abc(Q0, Q1, Q2, a, bb, cc);
        } else {
            ld(pn, Q0, Q1, Q2);
            abc(P0, P1, P2, a, bb, cc);
        }

        float res[4];
        #pragma unroll
        for (int j = 0; j < 4; ++j) {
            float ed = ed0[j] + a[j];
            float eh = eh0[j] + bb[j];
            float ew = ew0[j] + cc[j];
            float m  = ed * ed + eh * eh + ew * ew + 1e-6f;
            res[j] = m * rsqrt_approx(m);          // sqrt(m)
            ed0[j] = ed1[j] + 2.f * a[j];
            eh0[j] = eh1[j] + 2.f * bb[j];
            ew0[j] = ew1[j];
            ed1[j] = a[j]; eh1[j] = bb[j]; ew1[j] = -cc[j];
        }
        *(float4*)(orow + (long long)i * HW) =
            make_float4(res[0], res[1], res[2], res[3]);
    }
}

extern "C" void kernel_launch(void* const* d_in, const int* in_sizes, int n_in,
                              void* d_out, int out_size)
{
    const float* x = (const float*)d_in[0];
    float* out = (float*)d_out;
    dim3 grid(Hd / HT, Dd / ND, BCn);   // (16, 4, 32) = 2048 blocks
    dim3 block(32, 8);                  // 256 threads
    sobel3d_kernel<<<grid, block>>>(x, out);
}